// round 1
// baseline (speedup 1.0000x reference)
#include <cuda_runtime.h>

// B=16, TQ=TP=DQ=DP=1024
// inputs (metadata order): q [16,1024,1024] f32, p [16,1024,1024] f32, W [1024,1024] f32
// output: out [16,1024,1024] f32 = softmax_over_Tp((p@W)@q^T) @ q

static const long TT = 1024L * 1024L;

// Scratch (device globals — no runtime allocation)
__device__ float g_pW[16L * 1024 * 1024];  // 64 MB
__device__ float g_S [16L * 1024 * 1024];  // 64 MB
__device__ float g_m [16 * 1024];
__device__ float g_rZ[16 * 1024];

// MODE 0: C = A @ B           (A [M,K] rm, B [K,N] rm)
// MODE 1: C = A @ B^T         (A [M,K] rm, B [N,K] rm)
// MODE 2: C = f(A) @ B        (NN; f applied per A element: exp(a - m[k]) * rZ[k])
template<int MODE>
__global__ void __launch_bounds__(256, 2)
sgemm128(const float* __restrict__ Ag, const float* __restrict__ Bg,
         float* __restrict__ Cg,
         const float* __restrict__ Mv, const float* __restrict__ Zv,
         long strideA, long strideB)
{
    __shared__ float As[8][132];
    __shared__ float Bs[8][132];

    const int b = blockIdx.z;
    const float* A  = Ag + (long)b * strideA;
    const float* Bp = Bg + (long)b * strideB;
    float*       C  = Cg + (long)b * TT;

    const int tid = threadIdx.x;
    const int m0 = blockIdx.y * 128;
    const int n0 = blockIdx.x * 128;

    // A-tile (and NT B-tile) loader indices: 128 rows x 8 k, float4 per thread
    const int arow  = tid >> 1;
    const int acol4 = (tid & 1) << 2;
    // NN B-tile loader: 8 k-rows x 128 n, float4 per thread
    const int brow  = tid >> 5;
    const int bcol4 = (tid & 31) << 2;

    const int ty = tid >> 4;   // 0..15
    const int tx = tid & 15;   // 0..15

    float acc[8][8];
    #pragma unroll
    for (int i = 0; i < 8; i++)
        #pragma unroll
        for (int j = 0; j < 8; j++) acc[i][j] = 0.f;

    const float* mb = (MODE == 2) ? (Mv + b * 1024) : nullptr;
    const float* zb = (MODE == 2) ? (Zv + b * 1024) : nullptr;

    for (int k0 = 0; k0 < 1024; k0 += 8) {
        // ---- load A tile (transposed into As[k][m]) ----
        float4 av = *(const float4*)(A + (long)(m0 + arow) * 1024 + k0 + acol4);
        if (MODE == 2) {
            float4 mm = *(const float4*)(mb + k0 + acol4);
            float4 zz = *(const float4*)(zb + k0 + acol4);
            av.x = __expf(av.x - mm.x) * zz.x;
            av.y = __expf(av.y - mm.y) * zz.y;
            av.z = __expf(av.z - mm.z) * zz.z;
            av.w = __expf(av.w - mm.w) * zz.w;
        }
        As[acol4 + 0][arow] = av.x;
        As[acol4 + 1][arow] = av.y;
        As[acol4 + 2][arow] = av.z;
        As[acol4 + 3][arow] = av.w;

        // ---- load B tile into Bs[k][n] ----
        if (MODE == 1) {
            float4 bv = *(const float4*)(Bp + (long)(n0 + arow) * 1024 + k0 + acol4);
            Bs[acol4 + 0][arow] = bv.x;
            Bs[acol4 + 1][arow] = bv.y;
            Bs[acol4 + 2][arow] = bv.z;
            Bs[acol4 + 3][arow] = bv.w;
        } else {
            float4 bv = *(const float4*)(Bp + (long)(k0 + brow) * 1024 + n0 + bcol4);
            *(float4*)&Bs[brow][bcol4] = bv;
        }
        __syncthreads();

        #pragma unroll
        for (int kk = 0; kk < 8; kk++) {
            float4 a0 = *(const float4*)&As[kk][ty * 8];
            float4 a1 = *(const float4*)&As[kk][ty * 8 + 4];
            float4 b0 = *(const float4*)&Bs[kk][tx * 8];
            float4 b1 = *(const float4*)&Bs[kk][tx * 8 + 4];
            float ar[8] = {a0.x, a0.y, a0.z, a0.w, a1.x, a1.y, a1.z, a1.w};
            float br[8] = {b0.x, b0.y, b0.z, b0.w, b1.x, b1.y, b1.z, b1.w};
            #pragma unroll
            for (int i = 0; i < 8; i++)
                #pragma unroll
                for (int j = 0; j < 8; j++)
                    acc[i][j] = fmaf(ar[i], br[j], acc[i][j]);
        }
        __syncthreads();
    }

    #pragma unroll
    for (int i = 0; i < 8; i++) {
        float* crow = C + (long)(m0 + ty * 8 + i) * 1024 + n0 + tx * 8;
        float4 c0 = {acc[i][0], acc[i][1], acc[i][2], acc[i][3]};
        float4 c1 = {acc[i][4], acc[i][5], acc[i][6], acc[i][7]};
        *(float4*)(crow)     = c0;
        *(float4*)(crow + 4) = c1;
    }
}

// Column softmax stats over the Tp axis (rows) of S[b] in [Tp, Tq] row-major:
// one thread per (b, q) column: m[q] = max_p S[p,q], rZ[q] = 1 / sum_p exp(S[p,q]-m)
__global__ void __launch_bounds__(256)
col_softmax_stats(const float* __restrict__ S, float* __restrict__ Mv, float* __restrict__ Zv)
{
    const int b = blockIdx.y;
    const int q = blockIdx.x * 256 + threadIdx.x;
    const float* Sb = S + (long)b * TT + q;

    float m = -1e30f;
    #pragma unroll 8
    for (int p = 0; p < 1024; p++)
        m = fmaxf(m, Sb[(long)p << 10]);

    float z = 0.f;
    #pragma unroll 8
    for (int p = 0; p < 1024; p++)
        z += __expf(Sb[(long)p << 10] - m);

    Mv[b * 1024 + q] = m;
    Zv[b * 1024 + q] = 1.0f / z;
}

extern "C" void kernel_launch(void* const* d_in, const int* in_sizes, int n_in,
                              void* d_out, int out_size)
{
    const float* q = (const float*)d_in[0];
    const float* p = (const float*)d_in[1];
    const float* W = (const float*)d_in[2];
    float* out = (float*)d_out;

    float *pW, *S, *mv, *zv;
    cudaGetSymbolAddress((void**)&pW, g_pW);
    cudaGetSymbolAddress((void**)&S,  g_S);
    cudaGetSymbolAddress((void**)&mv, g_m);
    cudaGetSymbolAddress((void**)&zv, g_rZ);

    dim3 grid(8, 8, 16);
    dim3 block(256);

    // 1) pW[b] = p[b] @ W                       (NN)
    sgemm128<0><<<grid, block>>>(p, W, pW, nullptr, nullptr, TT, 0L);
    // 2) S[b]  = pW[b] @ q[b]^T                 (NT)
    sgemm128<1><<<grid, block>>>(pW, q, S, nullptr, nullptr, TT, TT);
    // 3) column softmax stats over Tp
    col_softmax_stats<<<dim3(4, 16), block>>>(S, mv, zv);
    // 4) out[b] = (exp(S[b]-m)*rZ) @ q[b]       (NN + transform)
    sgemm128<2><<<grid, block>>>(S, q, out, mv, zv, TT, TT);
}

// round 3
// speedup vs baseline: 2.2070x; 2.2070x over previous
#include <cuda_runtime.h>
#include <cuda_bf16.h>
#include <cstdint>

// B=16, TQ=TP=DQ=DP=1024
// out = softmax_over_Tp((p@W)@q^T) @ q, fp32 in/out.
// GEMMs on mma.sync.m16n8k16 bf16 with 2-way split, 3 products (hh+hl+lh).

static const long TT = 1048576L;

// ---------------- scratch ----------------
__device__ __nv_bfloat16 g_qhi[16777216], g_qlo[16777216];
__device__ __nv_bfloat16 g_phi[16777216], g_plo[16777216];
__device__ __nv_bfloat16 g_qThi[16777216], g_qTlo[16777216];
__device__ __nv_bfloat16 g_Wthi[1048576],  g_Wtlo[1048576];
__device__ __nv_bfloat16 g_pWhi[16777216], g_pWlo[16777216];
__device__ __nv_bfloat16 g_Ehi[16777216],  g_Elo[16777216];
__device__ float g_S[16777216];
__device__ float g_m[16384], g_rZ[16384];

// ---------------- asm helpers ----------------
__device__ __forceinline__ uint32_t smem_u32(const void* p) {
    uint32_t a;
    asm("{ .reg .u64 t; cvta.to.shared.u64 t, %1; cvt.u32.u64 %0, t; }" : "=r"(a) : "l"(p));
    return a;
}
__device__ __forceinline__ void cp16(uint32_t s, const void* g) {
    asm volatile("cp.async.cg.shared.global [%0], [%1], 16;" :: "r"(s), "l"(g));
}
__device__ __forceinline__ void cp_commit() { asm volatile("cp.async.commit_group;"); }
__device__ __forceinline__ void cp_wait0()  { asm volatile("cp.async.wait_group 0;"); }

__device__ __forceinline__ void ldsm4(uint32_t (&r)[4], uint32_t a) {
    asm volatile("ldmatrix.sync.aligned.m8n8.x4.shared.b16 {%0,%1,%2,%3}, [%4];"
                 : "=r"(r[0]), "=r"(r[1]), "=r"(r[2]), "=r"(r[3]) : "r"(a));
}
__device__ __forceinline__ void mma16816(float (&d)[4], const uint32_t (&a)[4],
                                         uint32_t b0, uint32_t b1) {
    asm volatile(
        "mma.sync.aligned.m16n8k16.row.col.f32.bf16.bf16.f32 "
        "{%0,%1,%2,%3}, {%4,%5,%6,%7}, {%8,%9}, {%0,%1,%2,%3};"
        : "+f"(d[0]), "+f"(d[1]), "+f"(d[2]), "+f"(d[3])
        : "r"(a[0]), "r"(a[1]), "r"(a[2]), "r"(a[3]), "r"(b0), "r"(b1));
}

// ---------------- GEMM: C[b][m][n] = sum_k A[b][m][k] * B[b][n][k] ----------------
// CTA tile 128x128x32, 8 warps (2m x 4n), warp tile 64x32.
static constexpr int ROWB   = 80;          // smem bytes/row (64B data + 16B pad)
static constexpr int MATB   = 128 * ROWB;  // 10240 per matrix tile
static constexpr int STAGEB = 4 * MATB;    // Ahi,Alo,Bhi,Blo
static constexpr int SMEMSZ = 2 * STAGEB;  // 81920

template<int STORE_SPLIT>
__global__ void __launch_bounds__(256, 1)
gemm_mma(const __nv_bfloat16* __restrict__ Ahi, const __nv_bfloat16* __restrict__ Alo, long sA,
         const __nv_bfloat16* __restrict__ Bhi, const __nv_bfloat16* __restrict__ Blo, long sB,
         float* __restrict__ Cf, __nv_bfloat16* __restrict__ Chi, __nv_bfloat16* __restrict__ Clo)
{
    extern __shared__ char smem[];
    const uint32_t sbase = smem_u32(smem);
    const int tid = threadIdx.x, lane = tid & 31, wid = tid >> 5;
    const int wm = wid >> 2, wn = wid & 3;
    const int b = blockIdx.z, m0 = blockIdx.y * 128, n0 = blockIdx.x * 128;

    const char* gA[2] = { (const char*)(Ahi + (size_t)b * sA + (size_t)m0 * 1024),
                          (const char*)(Alo + (size_t)b * sA + (size_t)m0 * 1024) };
    const char* gB[2] = { (const char*)(Bhi + (size_t)b * sB + (size_t)n0 * 1024),
                          (const char*)(Blo + (size_t)b * sB + (size_t)n0 * 1024) };

    // copy: per matrix 512 x 16B chunks; thread does chunks tid, tid+256
    const int c0row = tid >> 2, c0col = (tid & 3) * 16;          // chunk tid
    const int c1row = (tid + 256) >> 2, c1col = c0col;           // chunk tid+256

    auto issue_stage = [&](int buf, int kt) {
        const uint32_t sb = sbase + buf * STAGEB;
        const size_t kb = (size_t)kt * 64;   // byte offset of k0 within a row
        #pragma unroll
        for (int m = 0; m < 4; m++) {
            const char* g = (m < 2) ? gA[m] : gB[m - 2];
            const uint32_t so = sb + m * MATB;
            cp16(so + c0row * ROWB + c0col, g + (size_t)c0row * 2048 + kb + c0col);
            cp16(so + c1row * ROWB + c1col, g + (size_t)c1row * 2048 + kb + c1col);
        }
        cp_commit();
    };

    float acc[4][4][4];
    #pragma unroll
    for (int i = 0; i < 4; i++)
        #pragma unroll
        for (int j = 0; j < 4; j++)
            #pragma unroll
            for (int t = 0; t < 4; t++) acc[i][j][t] = 0.f;

    issue_stage(0, 0);

    // ldmatrix lane addressing: row = lane%16, colgrp = lane/16 (x8 elems)
    const int lrow = lane & 15, lcg = (lane >> 4) * 8;

    #pragma unroll 1
    for (int i = 0; i < 32; i++) {
        cp_wait0();
        __syncthreads();
        if (i < 31) issue_stage((i + 1) & 1, i + 1);

        const uint32_t sb = sbase + (i & 1) * STAGEB;
        const uint32_t sAh = sb, sAl = sb + MATB, sBh = sb + 2 * MATB, sBl = sb + 3 * MATB;

        #pragma unroll
        for (int ks = 0; ks < 2; ks++) {
            const uint32_t kb = (ks * 16 + lcg) * 2;
            uint32_t ah[4][4], al[4][4];
            #pragma unroll
            for (int mi = 0; mi < 4; mi++) {
                const uint32_t ro = (uint32_t)(wm * 64 + mi * 16 + lrow) * ROWB + kb;
                ldsm4(ah[mi], sAh + ro);
                ldsm4(al[mi], sAl + ro);
            }
            uint32_t bh[4][2], bl[4][2];
            #pragma unroll
            for (int nj = 0; nj < 2; nj++) {
                const uint32_t ro = (uint32_t)(wn * 32 + nj * 16 + lrow) * ROWB + kb;
                uint32_t r[4];
                ldsm4(r, sBh + ro);
                bh[2*nj][0] = r[0]; bh[2*nj+1][0] = r[1];
                bh[2*nj][1] = r[2]; bh[2*nj+1][1] = r[3];
                ldsm4(r, sBl + ro);
                bl[2*nj][0] = r[0]; bl[2*nj+1][0] = r[1];
                bl[2*nj][1] = r[2]; bl[2*nj+1][1] = r[3];
            }
            #pragma unroll
            for (int mi = 0; mi < 4; mi++)
                #pragma unroll
                for (int ni = 0; ni < 4; ni++) {
                    mma16816(acc[mi][ni], ah[mi], bh[ni][0], bh[ni][1]);  // hh
                    mma16816(acc[mi][ni], ah[mi], bl[ni][0], bl[ni][1]);  // hl
                    mma16816(acc[mi][ni], al[mi], bh[ni][0], bh[ni][1]);  // lh
                }
        }
        __syncthreads();
    }

    // epilogue: c0,c1 -> (row=lane/4, col=(lane%4)*2); c2,c3 -> row+8
    const int er = m0 + wm * 64 + (lane >> 2);
    const int ec = n0 + wn * 32 + (lane & 3) * 2;
    #pragma unroll
    for (int mi = 0; mi < 4; mi++)
        #pragma unroll
        for (int ni = 0; ni < 4; ni++) {
            const int r0 = er + mi * 16, c = ec + ni * 8;
            const size_t o0 = (size_t)b * TT + (size_t)r0 * 1024 + c;
            const size_t o1 = o0 + 8 * 1024;
            if (STORE_SPLIT == 0) {
                *(float2*)(Cf + o0) = make_float2(acc[mi][ni][0], acc[mi][ni][1]);
                *(float2*)(Cf + o1) = make_float2(acc[mi][ni][2], acc[mi][ni][3]);
            } else {
                #pragma unroll
                for (int h = 0; h < 2; h++) {
                    const size_t o = h ? o1 : o0;
                    float x0 = acc[mi][ni][2*h], x1 = acc[mi][ni][2*h+1];
                    __nv_bfloat16 h0 = __float2bfloat16(x0);
                    __nv_bfloat16 h1 = __float2bfloat16(x1);
                    __nv_bfloat16 l0 = __float2bfloat16(x0 - __bfloat162float(h0));
                    __nv_bfloat16 l1 = __float2bfloat16(x1 - __bfloat162float(h1));
                    __nv_bfloat162 hp; hp.x = h0; hp.y = h1;
                    __nv_bfloat162 lp; lp.x = l0; lp.y = l1;
                    *(__nv_bfloat162*)(Chi + o) = hp;
                    *(__nv_bfloat162*)(Clo + o) = lp;
                }
            }
        }
}

// ---------------- elementwise / transpose / softmax ----------------
struct alignas(8) bh4 { __nv_bfloat16 a, b, c, d; };

__device__ __forceinline__ void split1(float x, __nv_bfloat16& h, __nv_bfloat16& l) {
    h = __float2bfloat16(x);
    l = __float2bfloat16(x - __bfloat162float(h));
}

__global__ void __launch_bounds__(256)
split2_kernel(const float* __restrict__ X, __nv_bfloat16* __restrict__ hi,
              __nv_bfloat16* __restrict__ lo)
{
    size_t i = (size_t)blockIdx.x * 256 + threadIdx.x;
    float4 v = ((const float4*)X)[i];
    bh4 h, l;
    split1(v.x, h.a, l.a); split1(v.y, h.b, l.b);
    split1(v.z, h.c, l.c); split1(v.w, h.d, l.d);
    ((bh4*)hi)[i] = h;
    ((bh4*)lo)[i] = l;
}

__global__ void __launch_bounds__(256)
transpose_split_kernel(const float* __restrict__ in, __nv_bfloat16* __restrict__ ohi,
                       __nv_bfloat16* __restrict__ olo)
{
    __shared__ float t[32][33];
    const int b = blockIdx.z;
    const float* I = in + (size_t)b * TT;
    const int x = blockIdx.x * 32 + threadIdx.x;
    const int y = blockIdx.y * 32 + threadIdx.y;
    #pragma unroll
    for (int j = 0; j < 32; j += 8)
        t[threadIdx.y + j][threadIdx.x] = I[(size_t)(y + j) * 1024 + x];
    __syncthreads();
    const int ox = blockIdx.y * 32 + threadIdx.x;
    const int oy = blockIdx.x * 32 + threadIdx.y;
    const size_t ob = (size_t)b * TT;
    #pragma unroll
    for (int j = 0; j < 32; j += 8) {
        float v = t[threadIdx.x][threadIdx.y + j];
        __nv_bfloat16 h, l; split1(v, h, l);
        ohi[ob + (size_t)(oy + j) * 1024 + ox] = h;
        olo[ob + (size_t)(oy + j) * 1024 + ox] = l;
    }
}

__global__ void __launch_bounds__(256)
col_softmax_stats(const float* __restrict__ S, float* __restrict__ Mv, float* __restrict__ Zv)
{
    const int b = blockIdx.y;
    const int q = blockIdx.x * 256 + threadIdx.x;
    const float* Sb = S + (size_t)b * TT + q;
    float m = -1e30f;
    #pragma unroll 8
    for (int p = 0; p < 1024; p++) m = fmaxf(m, Sb[(size_t)p << 10]);
    float z = 0.f;
    #pragma unroll 8
    for (int p = 0; p < 1024; p++) z += __expf(Sb[(size_t)p << 10] - m);
    Mv[b * 1024 + q] = m;
    Zv[b * 1024 + q] = 1.0f / z;
}

__global__ void __launch_bounds__(256)
exp_split_kernel(const float* __restrict__ S, const float* __restrict__ Mv,
                 const float* __restrict__ Zv, __nv_bfloat16* __restrict__ Ehi,
                 __nv_bfloat16* __restrict__ Elo)
{
    size_t i = (size_t)blockIdx.x * 256 + threadIdx.x;
    size_t e = i * 4;
    int b = (int)(e >> 20);
    int col = (int)(e & 1023);
    float4 s = *(const float4*)(S + e);
    float4 m = *(const float4*)(Mv + b * 1024 + col);
    float4 z = *(const float4*)(Zv + b * 1024 + col);
    float4 w;
    w.x = __expf(s.x - m.x) * z.x;
    w.y = __expf(s.y - m.y) * z.y;
    w.z = __expf(s.z - m.z) * z.z;
    w.w = __expf(s.w - m.w) * z.w;
    bh4 h, l;
    split1(w.x, h.a, l.a); split1(w.y, h.b, l.b);
    split1(w.z, h.c, l.c); split1(w.w, h.d, l.d);
    ((bh4*)Ehi)[i] = h;
    ((bh4*)Elo)[i] = l;
}

// ---------------- launcher ----------------
extern "C" void kernel_launch(void* const* d_in, const int* in_sizes, int n_in,
                              void* d_out, int out_size)
{
    const float* q = (const float*)d_in[0];
    const float* p = (const float*)d_in[1];
    const float* W = (const float*)d_in[2];
    float* out = (float*)d_out;

    __nv_bfloat16 *qhi, *qlo, *phi, *plo, *qThi, *qTlo, *Wthi, *Wtlo, *pWhi, *pWlo, *Ehi, *Elo;
    float *S, *mv, *zv;
    cudaGetSymbolAddress((void**)&qhi, g_qhi);   cudaGetSymbolAddress((void**)&qlo, g_qlo);
    cudaGetSymbolAddress((void**)&phi, g_phi);   cudaGetSymbolAddress((void**)&plo, g_plo);
    cudaGetSymbolAddress((void**)&qThi, g_qThi); cudaGetSymbolAddress((void**)&qTlo, g_qTlo);
    cudaGetSymbolAddress((void**)&Wthi, g_Wthi); cudaGetSymbolAddress((void**)&Wtlo, g_Wtlo);
    cudaGetSymbolAddress((void**)&pWhi, g_pWhi); cudaGetSymbolAddress((void**)&pWlo, g_pWlo);
    cudaGetSymbolAddress((void**)&Ehi, g_Ehi);   cudaGetSymbolAddress((void**)&Elo, g_Elo);
    cudaGetSymbolAddress((void**)&S, g_S);
    cudaGetSymbolAddress((void**)&mv, g_m);      cudaGetSymbolAddress((void**)&zv, g_rZ);

    cudaFuncSetAttribute(gemm_mma<0>, cudaFuncAttributeMaxDynamicSharedMemorySize, SMEMSZ);
    cudaFuncSetAttribute(gemm_mma<1>, cudaFuncAttributeMaxDynamicSharedMemorySize, SMEMSZ);

    const dim3 ggrid(8, 8, 16);

    split2_kernel<<<16384, 256>>>(q, qhi, qlo);
    split2_kernel<<<16384, 256>>>(p, phi, plo);
    transpose_split_kernel<<<dim3(32, 32, 1),  dim3(32, 8)>>>(W, Wthi, Wtlo);
    transpose_split_kernel<<<dim3(32, 32, 16), dim3(32, 8)>>>(q, qThi, qTlo);

    // GEMM1: pW = p @ W   (B = W^T K-major), split-store
    gemm_mma<1><<<ggrid, 256, SMEMSZ>>>(phi, plo, TT, Wthi, Wtlo, 0L,
                                        nullptr, pWhi, pWlo);
    // GEMM2: S = pW @ q^T -> fp32
    gemm_mma<0><<<ggrid, 256, SMEMSZ>>>(pWhi, pWlo, TT, qhi, qlo, TT,
                                        S, nullptr, nullptr);
    col_softmax_stats<<<dim3(4, 16), 256>>>(S, mv, zv);
    exp_split_kernel<<<16384, 256>>>(S, mv, zv, Ehi, Elo);
    // GEMM3: out = E @ q  (B = q^T K-major) -> fp32
    gemm_mma<0><<<ggrid, 256, SMEMSZ>>>(Ehi, Elo, TT, qThi, qTlo, TT,
                                        out, nullptr, nullptr);
}

// round 4
// speedup vs baseline: 2.4826x; 1.1249x over previous
#include <cuda_runtime.h>
#include <cuda_bf16.h>
#include <cstdint>

// B=16, TQ=TP=DQ=DP=1024
// out = softmax_over_Tp((p@W)@q^T) @ q, fp32 in/out.
// GEMMs: mma.sync.m16n8k16 bf16, 2-way split, 3 products (hh+hl+lh).
// 128x128x64 CTA tile, 3-stage cp.async pipeline, XOR-swizzled smem.

static const long TT = 1048576L;

// ---------------- scratch ----------------
__device__ __nv_bfloat16 g_qhi[16777216], g_qlo[16777216];
__device__ __nv_bfloat16 g_phi[16777216], g_plo[16777216];
__device__ __nv_bfloat16 g_qThi[16777216], g_qTlo[16777216];
__device__ __nv_bfloat16 g_Wthi[1048576],  g_Wtlo[1048576];
__device__ __nv_bfloat16 g_pWhi[16777216], g_pWlo[16777216];
__device__ __nv_bfloat16 g_Ehi[16777216],  g_Elo[16777216];
__device__ float g_S[16777216];
__device__ float g_m[16384], g_rZ[16384];

// ---------------- asm helpers ----------------
__device__ __forceinline__ uint32_t smem_u32(const void* p) {
    uint32_t a;
    asm("{ .reg .u64 t; cvta.to.shared.u64 t, %1; cvt.u32.u64 %0, t; }" : "=r"(a) : "l"(p));
    return a;
}
__device__ __forceinline__ void cp16(uint32_t s, const void* g) {
    asm volatile("cp.async.cg.shared.global [%0], [%1], 16;" :: "r"(s), "l"(g));
}
__device__ __forceinline__ void cp_commit() { asm volatile("cp.async.commit_group;"); }
template<int N>
__device__ __forceinline__ void cp_wait() { asm volatile("cp.async.wait_group %0;" :: "n"(N)); }

__device__ __forceinline__ void ldsm4(uint32_t (&r)[4], uint32_t a) {
    asm volatile("ldmatrix.sync.aligned.m8n8.x4.shared.b16 {%0,%1,%2,%3}, [%4];"
                 : "=r"(r[0]), "=r"(r[1]), "=r"(r[2]), "=r"(r[3]) : "r"(a));
}
__device__ __forceinline__ void mma16816(float (&d)[4], const uint32_t (&a)[4],
                                         uint32_t b0, uint32_t b1) {
    asm volatile(
        "mma.sync.aligned.m16n8k16.row.col.f32.bf16.bf16.f32 "
        "{%0,%1,%2,%3}, {%4,%5,%6,%7}, {%8,%9}, {%0,%1,%2,%3};"
        : "+f"(d[0]), "+f"(d[1]), "+f"(d[2]), "+f"(d[3])
        : "r"(a[0]), "r"(a[1]), "r"(a[2]), "r"(a[3]), "r"(b0), "r"(b1));
}

// ---------------- GEMM: C[b][m][n] = sum_k A[b][m][k] * B[b][n][k] ----------------
// CTA tile 128x128, K-chunk 64 (128B rows, swizzled), 8 warps (2m x 4n), 3 stages.
static constexpr int MATB   = 128 * 128;   // 16KB per matrix tile
static constexpr int STAGEB = 4 * MATB;    // Ahi,Alo,Bhi,Blo = 64KB
static constexpr int SMEMSZ = 3 * STAGEB;  // 192KB

template<int STORE_SPLIT>
__global__ void __launch_bounds__(256, 1)
gemm_mma(const __nv_bfloat16* __restrict__ Ahi, const __nv_bfloat16* __restrict__ Alo, long sA,
         const __nv_bfloat16* __restrict__ Bhi, const __nv_bfloat16* __restrict__ Blo, long sB,
         float* __restrict__ Cf, __nv_bfloat16* __restrict__ Chi, __nv_bfloat16* __restrict__ Clo)
{
    extern __shared__ char smem[];
    const uint32_t sbase = smem_u32(smem);
    const int tid = threadIdx.x, lane = tid & 31, wid = tid >> 5;
    const int wm = wid >> 2, wn = wid & 3;
    const int b = blockIdx.z, m0 = blockIdx.y * 128, n0 = blockIdx.x * 128;

    const char* gA[2] = { (const char*)(Ahi + (size_t)b * sA + (size_t)m0 * 1024),
                          (const char*)(Alo + (size_t)b * sA + (size_t)m0 * 1024) };
    const char* gB[2] = { (const char*)(Bhi + (size_t)b * sB + (size_t)n0 * 1024),
                          (const char*)(Blo + (size_t)b * sB + (size_t)n0 * 1024) };

    // copy mapping: per matrix 1024 x 16B chunks, thread handles 4
    const int crow[4] = { tid >> 3, (tid + 256) >> 3, (tid + 512) >> 3, (tid + 768) >> 3 };
    const int ccol = tid & 7;   // chunk within row (same for all 4)

    auto issue_stage = [&](int buf, int kt) {
        const uint32_t sb = sbase + buf * STAGEB;
        const size_t kb = (size_t)kt * 128;   // byte offset of k0 within 2048B row
        #pragma unroll
        for (int m = 0; m < 4; m++) {
            const char* g = (m < 2) ? gA[m] : gB[m - 2];
            const uint32_t mb = sb + m * MATB;
            #pragma unroll
            for (int t = 0; t < 4; t++) {
                const int r = crow[t];
                cp16(mb + r * 128 + ((ccol ^ (r & 7)) * 16),
                     g + (size_t)r * 2048 + kb + ccol * 16);
            }
        }
        cp_commit();
    };

    float acc[4][4][4];
    #pragma unroll
    for (int i = 0; i < 4; i++)
        #pragma unroll
        for (int j = 0; j < 4; j++)
            #pragma unroll
            for (int t = 0; t < 4; t++) acc[i][j][t] = 0.f;

    issue_stage(0, 0);
    issue_stage(1, 1);

    // ldmatrix lane addressing: row = lane%16, hi-half selector = lane/16
    const int lrow = lane & 15, lhi = lane >> 4;
    const int swz = lrow & 7;
    // per-ks swizzled byte offset of the 16B chunk this lane reads
    uint32_t koff[4];
    #pragma unroll
    for (int ks = 0; ks < 4; ks++) koff[ks] = (uint32_t)(((ks * 2 + lhi) ^ swz) * 16);

    const uint32_t arow_off = (uint32_t)(wm * 64 + lrow) * 128;
    const uint32_t brow_off = (uint32_t)(wn * 32 + lrow) * 128;

    #pragma unroll 1
    for (int i = 0; i < 16; i++) {
        if (i < 15) cp_wait<1>(); else cp_wait<0>();
        __syncthreads();
        if (i + 2 < 16) issue_stage((i + 2) % 3, i + 2);

        const uint32_t sb = sbase + (i % 3) * STAGEB;
        const uint32_t sAh = sb, sAl = sb + MATB, sBh = sb + 2 * MATB, sBl = sb + 3 * MATB;

        #pragma unroll
        for (int ks = 0; ks < 4; ks++) {
            const uint32_t kb = koff[ks];
            uint32_t ah[4][4], al[4][4];
            #pragma unroll
            for (int mi = 0; mi < 4; mi++) {
                const uint32_t ro = arow_off + (uint32_t)(mi * 16) * 128 + kb;
                ldsm4(ah[mi], sAh + ro);
                ldsm4(al[mi], sAl + ro);
            }
            uint32_t bh[4][2], bl[4][2];
            #pragma unroll
            for (int nj = 0; nj < 2; nj++) {
                const uint32_t ro = brow_off + (uint32_t)(nj * 16) * 128 + kb;
                uint32_t r[4];
                ldsm4(r, sBh + ro);
                bh[2*nj][0] = r[0]; bh[2*nj+1][0] = r[1];
                bh[2*nj][1] = r[2]; bh[2*nj+1][1] = r[3];
                ldsm4(r, sBl + ro);
                bl[2*nj][0] = r[0]; bl[2*nj+1][0] = r[1];
                bl[2*nj][1] = r[2]; bl[2*nj+1][1] = r[3];
            }
            #pragma unroll
            for (int mi = 0; mi < 4; mi++)
                #pragma unroll
                for (int ni = 0; ni < 4; ni++) {
                    mma16816(acc[mi][ni], ah[mi], bh[ni][0], bh[ni][1]);  // hh
                    mma16816(acc[mi][ni], ah[mi], bl[ni][0], bl[ni][1]);  // hl
                    mma16816(acc[mi][ni], al[mi], bh[ni][0], bh[ni][1]);  // lh
                }
        }
    }

    // epilogue
    const int er = m0 + wm * 64 + (lane >> 2);
    const int ec = n0 + wn * 32 + (lane & 3) * 2;
    #pragma unroll
    for (int mi = 0; mi < 4; mi++)
        #pragma unroll
        for (int ni = 0; ni < 4; ni++) {
            const int r0 = er + mi * 16, c = ec + ni * 8;
            const size_t o0 = (size_t)b * TT + (size_t)r0 * 1024 + c;
            const size_t o1 = o0 + 8 * 1024;
            if (STORE_SPLIT == 0) {
                *(float2*)(Cf + o0) = make_float2(acc[mi][ni][0], acc[mi][ni][1]);
                *(float2*)(Cf + o1) = make_float2(acc[mi][ni][2], acc[mi][ni][3]);
            } else {
                #pragma unroll
                for (int h = 0; h < 2; h++) {
                    const size_t o = h ? o1 : o0;
                    float x0 = acc[mi][ni][2*h], x1 = acc[mi][ni][2*h+1];
                    __nv_bfloat16 h0 = __float2bfloat16(x0);
                    __nv_bfloat16 h1 = __float2bfloat16(x1);
                    __nv_bfloat16 l0 = __float2bfloat16(x0 - __bfloat162float(h0));
                    __nv_bfloat16 l1 = __float2bfloat16(x1 - __bfloat162float(h1));
                    __nv_bfloat162 hp; hp.x = h0; hp.y = h1;
                    __nv_bfloat162 lp; lp.x = l0; lp.y = l1;
                    *(__nv_bfloat162*)(Chi + o) = hp;
                    *(__nv_bfloat162*)(Clo + o) = lp;
                }
            }
        }
}

// ---------------- elementwise / transpose / softmax ----------------
struct alignas(8) bh4 { __nv_bfloat16 a, b, c, d; };

__device__ __forceinline__ void split1(float x, __nv_bfloat16& h, __nv_bfloat16& l) {
    h = __float2bfloat16(x);
    l = __float2bfloat16(x - __bfloat162float(h));
}

__global__ void __launch_bounds__(256)
split2_kernel(const float* __restrict__ X, __nv_bfloat16* __restrict__ hi,
              __nv_bfloat16* __restrict__ lo)
{
    size_t i = (size_t)blockIdx.x * 256 + threadIdx.x;
    float4 v = ((const float4*)X)[i];
    bh4 h, l;
    split1(v.x, h.a, l.a); split1(v.y, h.b, l.b);
    split1(v.z, h.c, l.c); split1(v.w, h.d, l.d);
    ((bh4*)hi)[i] = h;
    ((bh4*)lo)[i] = l;
}

// reads a 32x32 tile once; writes straight split (ohi/olo) and transposed split (thi/tlo)
__global__ void __launch_bounds__(256)
split_both_kernel(const float* __restrict__ in,
                  __nv_bfloat16* __restrict__ ohi, __nv_bfloat16* __restrict__ olo,
                  __nv_bfloat16* __restrict__ thi, __nv_bfloat16* __restrict__ tlo)
{
    __shared__ float t[32][33];
    const int b = blockIdx.z;
    const float* I = in + (size_t)b * TT;
    const int x = blockIdx.x * 32 + threadIdx.x;
    const int y = blockIdx.y * 32 + threadIdx.y;
    const size_t ob = (size_t)b * TT;
    #pragma unroll
    for (int j = 0; j < 32; j += 8) {
        float v = I[(size_t)(y + j) * 1024 + x];
        t[threadIdx.y + j][threadIdx.x] = v;
        __nv_bfloat16 h, l; split1(v, h, l);
        ohi[ob + (size_t)(y + j) * 1024 + x] = h;
        olo[ob + (size_t)(y + j) * 1024 + x] = l;
    }
    __syncthreads();
    const int ox = blockIdx.y * 32 + threadIdx.x;
    const int oy = blockIdx.x * 32 + threadIdx.y;
    #pragma unroll
    for (int j = 0; j < 32; j += 8) {
        float v = t[threadIdx.x][threadIdx.y + j];
        __nv_bfloat16 h, l; split1(v, h, l);
        thi[ob + (size_t)(oy + j) * 1024 + ox] = h;
        tlo[ob + (size_t)(oy + j) * 1024 + ox] = l;
    }
}

__global__ void __launch_bounds__(256)
transpose_split_kernel(const float* __restrict__ in, __nv_bfloat16* __restrict__ ohi,
                       __nv_bfloat16* __restrict__ olo)
{
    __shared__ float t[32][33];
    const int b = blockIdx.z;
    const float* I = in + (size_t)b * TT;
    const int x = blockIdx.x * 32 + threadIdx.x;
    const int y = blockIdx.y * 32 + threadIdx.y;
    #pragma unroll
    for (int j = 0; j < 32; j += 8)
        t[threadIdx.y + j][threadIdx.x] = I[(size_t)(y + j) * 1024 + x];
    __syncthreads();
    const int ox = blockIdx.y * 32 + threadIdx.x;
    const int oy = blockIdx.x * 32 + threadIdx.y;
    const size_t ob = (size_t)b * TT;
    #pragma unroll
    for (int j = 0; j < 32; j += 8) {
        float v = t[threadIdx.x][threadIdx.y + j];
        __nv_bfloat16 h, l; split1(v, h, l);
        ohi[ob + (size_t)(oy + j) * 1024 + ox] = h;
        olo[ob + (size_t)(oy + j) * 1024 + ox] = l;
    }
}

__global__ void __launch_bounds__(256)
col_softmax_stats(const float* __restrict__ S, float* __restrict__ Mv, float* __restrict__ Zv)
{
    const int b = blockIdx.y;
    const int q = blockIdx.x * 256 + threadIdx.x;
    const float* Sb = S + (size_t)b * TT + q;
    float m = -1e30f;
    #pragma unroll 8
    for (int p = 0; p < 1024; p++) m = fmaxf(m, Sb[(size_t)p << 10]);
    float z = 0.f;
    #pragma unroll 8
    for (int p = 0; p < 1024; p++) z += __expf(Sb[(size_t)p << 10] - m);
    Mv[b * 1024 + q] = m;
    Zv[b * 1024 + q] = 1.0f / z;
}

__global__ void __launch_bounds__(256)
exp_split_kernel(const float* __restrict__ S, const float* __restrict__ Mv,
                 const float* __restrict__ Zv, __nv_bfloat16* __restrict__ Ehi,
                 __nv_bfloat16* __restrict__ Elo)
{
    size_t i = (size_t)blockIdx.x * 256 + threadIdx.x;
    size_t e = i * 4;
    int b = (int)(e >> 20);
    int col = (int)(e & 1023);
    float4 s = *(const float4*)(S + e);
    float4 m = *(const float4*)(Mv + b * 1024 + col);
    float4 z = *(const float4*)(Zv + b * 1024 + col);
    float4 w;
    w.x = __expf(s.x - m.x) * z.x;
    w.y = __expf(s.y - m.y) * z.y;
    w.z = __expf(s.z - m.z) * z.z;
    w.w = __expf(s.w - m.w) * z.w;
    bh4 h, l;
    split1(w.x, h.a, l.a); split1(w.y, h.b, l.b);
    split1(w.z, h.c, l.c); split1(w.w, h.d, l.d);
    ((bh4*)Ehi)[i] = h;
    ((bh4*)Elo)[i] = l;
}

// ---------------- launcher ----------------
extern "C" void kernel_launch(void* const* d_in, const int* in_sizes, int n_in,
                              void* d_out, int out_size)
{
    const float* q = (const float*)d_in[0];
    const float* p = (const float*)d_in[1];
    const float* W = (const float*)d_in[2];
    float* out = (float*)d_out;

    __nv_bfloat16 *qhi, *qlo, *phi, *plo, *qThi, *qTlo, *Wthi, *Wtlo, *pWhi, *pWlo, *Ehi, *Elo;
    float *S, *mv, *zv;
    cudaGetSymbolAddress((void**)&qhi, g_qhi);   cudaGetSymbolAddress((void**)&qlo, g_qlo);
    cudaGetSymbolAddress((void**)&phi, g_phi);   cudaGetSymbolAddress((void**)&plo, g_plo);
    cudaGetSymbolAddress((void**)&qThi, g_qThi); cudaGetSymbolAddress((void**)&qTlo, g_qTlo);
    cudaGetSymbolAddress((void**)&Wthi, g_Wthi); cudaGetSymbolAddress((void**)&Wtlo, g_Wtlo);
    cudaGetSymbolAddress((void**)&pWhi, g_pWhi); cudaGetSymbolAddress((void**)&pWlo, g_pWlo);
    cudaGetSymbolAddress((void**)&Ehi, g_Ehi);   cudaGetSymbolAddress((void**)&Elo, g_Elo);
    cudaGetSymbolAddress((void**)&S, g_S);
    cudaGetSymbolAddress((void**)&mv, g_m);      cudaGetSymbolAddress((void**)&zv, g_rZ);

    cudaFuncSetAttribute(gemm_mma<0>, cudaFuncAttributeMaxDynamicSharedMemorySize, SMEMSZ);
    cudaFuncSetAttribute(gemm_mma<1>, cudaFuncAttributeMaxDynamicSharedMemorySize, SMEMSZ);

    const dim3 ggrid(8, 8, 16);

    split2_kernel<<<16384, 256>>>(p, phi, plo);
    split_both_kernel<<<dim3(32, 32, 16), dim3(32, 8)>>>(q, qhi, qlo, qThi, qTlo);
    transpose_split_kernel<<<dim3(32, 32, 1), dim3(32, 8)>>>(W, Wthi, Wtlo);

    // GEMM1: pW = p @ W   (B = W^T K-major), split-store
    gemm_mma<1><<<ggrid, 256, SMEMSZ>>>(phi, plo, TT, Wthi, Wtlo, 0L,
                                        nullptr, pWhi, pWlo);
    // GEMM2: S = pW @ q^T -> fp32
    gemm_mma<0><<<ggrid, 256, SMEMSZ>>>(pWhi, pWlo, TT, qhi, qlo, TT,
                                        S, nullptr, nullptr);
    col_softmax_stats<<<dim3(4, 16), 256>>>(S, mv, zv);
    exp_split_kernel<<<16384, 256>>>(S, mv, zv, Ehi, Elo);
    // GEMM3: out = E @ q  (B = q^T K-major) -> fp32
    gemm_mma<0><<<ggrid, 256, SMEMSZ>>>(Ehi, Elo, TT, qThi, qTlo, TT,
                                        out, nullptr, nullptr);
}

// round 5
// speedup vs baseline: 2.7763x; 1.1183x over previous
#include <cuda_runtime.h>
#include <cuda_bf16.h>
#include <cstdint>

// B=16, TQ=TP=DQ=DP=1024
// out = softmax_over_Tp((p@W)@q^T) @ q, fp32 in/out.
// GEMMs: mma.sync.m16n8k16 bf16, 2-way split, 3 products (hh+hl+lh).
// 128x128x64 CTA tile, 512 threads (16 warps, 32x32 warp tiles), 3-stage cp.async.

static const long TT = 1048576L;

// ---------------- scratch ----------------
__device__ __nv_bfloat16 g_qhi[16777216], g_qlo[16777216];
__device__ __nv_bfloat16 g_phi[16777216], g_plo[16777216];
__device__ __nv_bfloat16 g_qThi[16777216], g_qTlo[16777216];
__device__ __nv_bfloat16 g_Wthi[1048576],  g_Wtlo[1048576];
__device__ __nv_bfloat16 g_pWhi[16777216], g_pWlo[16777216];
__device__ __nv_bfloat16 g_Ehi[16777216],  g_Elo[16777216];
__device__ float g_S[16777216];

// ---------------- asm helpers ----------------
__device__ __forceinline__ uint32_t smem_u32(const void* p) {
    uint32_t a;
    asm("{ .reg .u64 t; cvta.to.shared.u64 t, %1; cvt.u32.u64 %0, t; }" : "=r"(a) : "l"(p));
    return a;
}
__device__ __forceinline__ void cp16(uint32_t s, const void* g) {
    asm volatile("cp.async.cg.shared.global [%0], [%1], 16;" :: "r"(s), "l"(g));
}
__device__ __forceinline__ void cp_commit() { asm volatile("cp.async.commit_group;"); }
template<int N>
__device__ __forceinline__ void cp_wait() { asm volatile("cp.async.wait_group %0;" :: "n"(N)); }

__device__ __forceinline__ void ldsm4(uint32_t (&r)[4], uint32_t a) {
    asm volatile("ldmatrix.sync.aligned.m8n8.x4.shared.b16 {%0,%1,%2,%3}, [%4];"
                 : "=r"(r[0]), "=r"(r[1]), "=r"(r[2]), "=r"(r[3]) : "r"(a));
}
__device__ __forceinline__ void mma16816(float (&d)[4], const uint32_t (&a)[4],
                                         uint32_t b0, uint32_t b1) {
    asm volatile(
        "mma.sync.aligned.m16n8k16.row.col.f32.bf16.bf16.f32 "
        "{%0,%1,%2,%3}, {%4,%5,%6,%7}, {%8,%9}, {%0,%1,%2,%3};"
        : "+f"(d[0]), "+f"(d[1]), "+f"(d[2]), "+f"(d[3])
        : "r"(a[0]), "r"(a[1]), "r"(a[2]), "r"(a[3]), "r"(b0), "r"(b1));
}

// ---------------- GEMM: C[b][m][n] = sum_k A[b][m][k] * B[b][n][k] ----------------
static constexpr int MATB   = 128 * 128;   // 16KB per matrix tile (128 rows x 128B)
static constexpr int STAGEB = 4 * MATB;    // Ahi,Alo,Bhi,Blo = 64KB
static constexpr int SMEMSZ = 3 * STAGEB;  // 192KB

template<int STORE_SPLIT>
__global__ void __launch_bounds__(512, 1)
gemm_mma(const __nv_bfloat16* __restrict__ Ahi, const __nv_bfloat16* __restrict__ Alo, long sA,
         const __nv_bfloat16* __restrict__ Bhi, const __nv_bfloat16* __restrict__ Blo, long sB,
         float* __restrict__ Cf, __nv_bfloat16* __restrict__ Chi, __nv_bfloat16* __restrict__ Clo)
{
    extern __shared__ char smem[];
    const uint32_t sbase = smem_u32(smem);
    const int tid = threadIdx.x, lane = tid & 31, wid = tid >> 5;
    const int wm = wid >> 2, wn = wid & 3;        // 4x4 warp grid, 32x32 warp tiles
    const int b = blockIdx.z, m0 = blockIdx.y * 128, n0 = blockIdx.x * 128;

    const char* gA[2] = { (const char*)(Ahi + (size_t)b * sA + (size_t)m0 * 1024),
                          (const char*)(Alo + (size_t)b * sA + (size_t)m0 * 1024) };
    const char* gB[2] = { (const char*)(Bhi + (size_t)b * sB + (size_t)n0 * 1024),
                          (const char*)(Blo + (size_t)b * sB + (size_t)n0 * 1024) };

    // loader: per matrix 1024 x 16B chunks, thread handles 2 (tid, tid+512)
    const int crow[2] = { tid >> 3, (tid + 512) >> 3 };
    const int ccol = tid & 7;

    auto issue_stage = [&](int buf, int kt) {
        const uint32_t sb = sbase + buf * STAGEB;
        const size_t kb = (size_t)kt * 128;   // byte offset of k0 within 2048B row
        #pragma unroll
        for (int m = 0; m < 4; m++) {
            const char* g = (m < 2) ? gA[m] : gB[m - 2];
            const uint32_t mb = sb + m * MATB;
            #pragma unroll
            for (int t = 0; t < 2; t++) {
                const int r = crow[t];
                cp16(mb + r * 128 + ((ccol ^ (r & 7)) * 16),
                     g + (size_t)r * 2048 + kb + ccol * 16);
            }
        }
        cp_commit();
    };

    float acc[2][4][4];
    #pragma unroll
    for (int i = 0; i < 2; i++)
        #pragma unroll
        for (int j = 0; j < 4; j++)
            #pragma unroll
            for (int t = 0; t < 4; t++) acc[i][j][t] = 0.f;

    issue_stage(0, 0);
    issue_stage(1, 1);

    // ldmatrix lane addressing
    const int lrow = lane & 15, lhi = lane >> 4;
    const int swz = lrow & 7;
    uint32_t koff[4];
    #pragma unroll
    for (int ks = 0; ks < 4; ks++) koff[ks] = (uint32_t)(((ks * 2 + lhi) ^ swz) * 16);

    const uint32_t arow_off = (uint32_t)(wm * 32 + lrow) * 128;
    const uint32_t brow_off = (uint32_t)(wn * 32 + lrow) * 128;

    #pragma unroll 1
    for (int i = 0; i < 16; i++) {
        if (i < 15) cp_wait<1>(); else cp_wait<0>();
        __syncthreads();
        if (i + 2 < 16) issue_stage((i + 2) % 3, i + 2);

        const uint32_t sb = sbase + (i % 3) * STAGEB;
        const uint32_t sAh = sb, sAl = sb + MATB, sBh = sb + 2 * MATB, sBl = sb + 3 * MATB;

        #pragma unroll
        for (int ks = 0; ks < 4; ks++) {
            const uint32_t kb = koff[ks];
            uint32_t ah[2][4], al[2][4];
            #pragma unroll
            for (int mi = 0; mi < 2; mi++) {
                const uint32_t ro = arow_off + (uint32_t)(mi * 16) * 128 + kb;
                ldsm4(ah[mi], sAh + ro);
                ldsm4(al[mi], sAl + ro);
            }
            uint32_t bh[4][2], bl[4][2];
            #pragma unroll
            for (int nj = 0; nj < 2; nj++) {
                const uint32_t ro = brow_off + (uint32_t)(nj * 16) * 128 + kb;
                uint32_t r[4];
                ldsm4(r, sBh + ro);
                bh[2*nj][0] = r[0]; bh[2*nj+1][0] = r[1];
                bh[2*nj][1] = r[2]; bh[2*nj+1][1] = r[3];
                ldsm4(r, sBl + ro);
                bl[2*nj][0] = r[0]; bl[2*nj+1][0] = r[1];
                bl[2*nj][1] = r[2]; bl[2*nj+1][1] = r[3];
            }
            #pragma unroll
            for (int mi = 0; mi < 2; mi++)
                #pragma unroll
                for (int ni = 0; ni < 4; ni++) {
                    mma16816(acc[mi][ni], ah[mi], bh[ni][0], bh[ni][1]);  // hh
                    mma16816(acc[mi][ni], ah[mi], bl[ni][0], bl[ni][1]);  // hl
                    mma16816(acc[mi][ni], al[mi], bh[ni][0], bh[ni][1]);  // lh
                }
        }
    }

    // epilogue
    const int er = m0 + wm * 32 + (lane >> 2);
    const int ec = n0 + wn * 32 + (lane & 3) * 2;
    #pragma unroll
    for (int mi = 0; mi < 2; mi++)
        #pragma unroll
        for (int ni = 0; ni < 4; ni++) {
            const int r0 = er + mi * 16, c = ec + ni * 8;
            const size_t o0 = (size_t)b * TT + (size_t)r0 * 1024 + c;
            const size_t o1 = o0 + 8 * 1024;
            if (STORE_SPLIT == 0) {
                *(float2*)(Cf + o0) = make_float2(acc[mi][ni][0], acc[mi][ni][1]);
                *(float2*)(Cf + o1) = make_float2(acc[mi][ni][2], acc[mi][ni][3]);
            } else {
                #pragma unroll
                for (int h = 0; h < 2; h++) {
                    const size_t o = h ? o1 : o0;
                    float x0 = acc[mi][ni][2*h], x1 = acc[mi][ni][2*h+1];
                    __nv_bfloat16 h0 = __float2bfloat16(x0);
                    __nv_bfloat16 h1 = __float2bfloat16(x1);
                    __nv_bfloat16 l0 = __float2bfloat16(x0 - __bfloat162float(h0));
                    __nv_bfloat16 l1 = __float2bfloat16(x1 - __bfloat162float(h1));
                    __nv_bfloat162 hp; hp.x = h0; hp.y = h1;
                    __nv_bfloat162 lp; lp.x = l0; lp.y = l1;
                    *(__nv_bfloat162*)(Chi + o) = hp;
                    *(__nv_bfloat162*)(Clo + o) = lp;
                }
            }
        }
}

// ---------------- elementwise / transpose / softmax ----------------
struct alignas(8) bh4 { __nv_bfloat16 a, b, c, d; };

__device__ __forceinline__ void split1(float x, __nv_bfloat16& h, __nv_bfloat16& l) {
    h = __float2bfloat16(x);
    l = __float2bfloat16(x - __bfloat162float(h));
}

__global__ void __launch_bounds__(256)
split2_kernel(const float* __restrict__ X, __nv_bfloat16* __restrict__ hi,
              __nv_bfloat16* __restrict__ lo)
{
    size_t i = (size_t)blockIdx.x * 256 + threadIdx.x;
    float4 v = ((const float4*)X)[i];
    bh4 h, l;
    split1(v.x, h.a, l.a); split1(v.y, h.b, l.b);
    split1(v.z, h.c, l.c); split1(v.w, h.d, l.d);
    ((bh4*)hi)[i] = h;
    ((bh4*)lo)[i] = l;
}

__global__ void __launch_bounds__(256)
split_both_kernel(const float* __restrict__ in,
                  __nv_bfloat16* __restrict__ ohi, __nv_bfloat16* __restrict__ olo,
                  __nv_bfloat16* __restrict__ thi, __nv_bfloat16* __restrict__ tlo)
{
    __shared__ float t[32][33];
    const int b = blockIdx.z;
    const float* I = in + (size_t)b * TT;
    const int x = blockIdx.x * 32 + threadIdx.x;
    const int y = blockIdx.y * 32 + threadIdx.y;
    const size_t ob = (size_t)b * TT;
    #pragma unroll
    for (int j = 0; j < 32; j += 8) {
        float v = I[(size_t)(y + j) * 1024 + x];
        t[threadIdx.y + j][threadIdx.x] = v;
        __nv_bfloat16 h, l; split1(v, h, l);
        ohi[ob + (size_t)(y + j) * 1024 + x] = h;
        olo[ob + (size_t)(y + j) * 1024 + x] = l;
    }
    __syncthreads();
    const int ox = blockIdx.y * 32 + threadIdx.x;
    const int oy = blockIdx.x * 32 + threadIdx.y;
    #pragma unroll
    for (int j = 0; j < 32; j += 8) {
        float v = t[threadIdx.x][threadIdx.y + j];
        __nv_bfloat16 h, l; split1(v, h, l);
        thi[ob + (size_t)(oy + j) * 1024 + ox] = h;
        tlo[ob + (size_t)(oy + j) * 1024 + ox] = l;
    }
}

__global__ void __launch_bounds__(256)
transpose_split_kernel(const float* __restrict__ in, __nv_bfloat16* __restrict__ ohi,
                       __nv_bfloat16* __restrict__ olo)
{
    __shared__ float t[32][33];
    const int b = blockIdx.z;
    const float* I = in + (size_t)b * TT;
    const int x = blockIdx.x * 32 + threadIdx.x;
    const int y = blockIdx.y * 32 + threadIdx.y;
    #pragma unroll
    for (int j = 0; j < 32; j += 8)
        t[threadIdx.y + j][threadIdx.x] = I[(size_t)(y + j) * 1024 + x];
    __syncthreads();
    const int ox = blockIdx.y * 32 + threadIdx.x;
    const int oy = blockIdx.x * 32 + threadIdx.y;
    const size_t ob = (size_t)b * TT;
    #pragma unroll
    for (int j = 0; j < 32; j += 8) {
        float v = t[threadIdx.x][threadIdx.y + j];
        __nv_bfloat16 h, l; split1(v, h, l);
        ohi[ob + (size_t)(oy + j) * 1024 + ox] = h;
        olo[ob + (size_t)(oy + j) * 1024 + ox] = l;
    }
}

// Fused column softmax (over Tp = rows of S[b]) + exp + bf16 split.
// One CTA per (32-column stripe, batch): online (m,z) pass, then exp pass (L2-hot reread).
__global__ void __launch_bounds__(256)
softmax_exp_split(const float* __restrict__ S,
                  __nv_bfloat16* __restrict__ Ehi, __nv_bfloat16* __restrict__ Elo)
{
    __shared__ float sm[8][32], sz[8][32];
    __shared__ float fm[32], fz[32];
    const int b = blockIdx.y;
    const int c = (threadIdx.x & 31);
    const int g = threadIdx.x >> 5;                 // row group 0..7
    const int col = blockIdx.x * 32 + c;
    const float* Sb = S + (size_t)b * TT + col;

    float m = -1e30f, z = 0.f;
    #pragma unroll 4
    for (int r = g; r < 1024; r += 8) {
        float x = Sb[(size_t)r << 10];
        if (x > m) { z = z * __expf(m - x) + 1.f; m = x; }
        else       { z += __expf(x - m); }
    }
    sm[g][c] = m; sz[g][c] = z;
    __syncthreads();
    if (threadIdx.x < 32) {
        float M = sm[0][c];
        #pragma unroll
        for (int i = 1; i < 8; i++) M = fmaxf(M, sm[i][c]);
        float Z = 0.f;
        #pragma unroll
        for (int i = 0; i < 8; i++) Z += sz[i][c] * __expf(sm[i][c] - M);
        fm[c] = M; fz[c] = 1.0f / Z;
    }
    __syncthreads();
    const float Mf = fm[c], Rf = fz[c];
    __nv_bfloat16* eh = Ehi + (size_t)b * TT + col;
    __nv_bfloat16* el = Elo + (size_t)b * TT + col;
    #pragma unroll 4
    for (int r = g; r < 1024; r += 8) {
        float x = Sb[(size_t)r << 10];
        float w = __expf(x - Mf) * Rf;
        __nv_bfloat16 h, l; split1(w, h, l);
        eh[(size_t)r << 10] = h;
        el[(size_t)r << 10] = l;
    }
}

// ---------------- launcher ----------------
extern "C" void kernel_launch(void* const* d_in, const int* in_sizes, int n_in,
                              void* d_out, int out_size)
{
    const float* q = (const float*)d_in[0];
    const float* p = (const float*)d_in[1];
    const float* W = (const float*)d_in[2];
    float* out = (float*)d_out;

    __nv_bfloat16 *qhi, *qlo, *phi, *plo, *qThi, *qTlo, *Wthi, *Wtlo, *pWhi, *pWlo, *Ehi, *Elo;
    float *S;
    cudaGetSymbolAddress((void**)&qhi, g_qhi);   cudaGetSymbolAddress((void**)&qlo, g_qlo);
    cudaGetSymbolAddress((void**)&phi, g_phi);   cudaGetSymbolAddress((void**)&plo, g_plo);
    cudaGetSymbolAddress((void**)&qThi, g_qThi); cudaGetSymbolAddress((void**)&qTlo, g_qTlo);
    cudaGetSymbolAddress((void**)&Wthi, g_Wthi); cudaGetSymbolAddress((void**)&Wtlo, g_Wtlo);
    cudaGetSymbolAddress((void**)&pWhi, g_pWhi); cudaGetSymbolAddress((void**)&pWlo, g_pWlo);
    cudaGetSymbolAddress((void**)&Ehi, g_Ehi);   cudaGetSymbolAddress((void**)&Elo, g_Elo);
    cudaGetSymbolAddress((void**)&S, g_S);

    cudaFuncSetAttribute(gemm_mma<0>, cudaFuncAttributeMaxDynamicSharedMemorySize, SMEMSZ);
    cudaFuncSetAttribute(gemm_mma<1>, cudaFuncAttributeMaxDynamicSharedMemorySize, SMEMSZ);

    const dim3 ggrid(8, 8, 16);

    split2_kernel<<<16384, 256>>>(p, phi, plo);
    split_both_kernel<<<dim3(32, 32, 16), dim3(32, 8)>>>(q, qhi, qlo, qThi, qTlo);
    transpose_split_kernel<<<dim3(32, 32, 1), dim3(32, 8)>>>(W, Wthi, Wtlo);

    // GEMM1: pW = p @ W   (B = W^T K-major), split-store
    gemm_mma<1><<<ggrid, 512, SMEMSZ>>>(phi, plo, TT, Wthi, Wtlo, 0L,
                                        nullptr, pWhi, pWlo);
    // GEMM2: S = pW @ q^T -> fp32
    gemm_mma<0><<<ggrid, 512, SMEMSZ>>>(pWhi, pWlo, TT, qhi, qlo, TT,
                                        S, nullptr, nullptr);
    // fused: column softmax stats + exp + split
    softmax_exp_split<<<dim3(32, 16), 256>>>(S, Ehi, Elo);
    // GEMM3: out = E @ q  (B = q^T K-major) -> fp32
    gemm_mma<0><<<ggrid, 512, SMEMSZ>>>(Ehi, Elo, TT, qThi, qTlo, TT,
                                        out, nullptr, nullptr);
}